// round 9
// baseline (speedup 1.0000x reference)
#include <cuda_runtime.h>
#include <cuda_bf16.h>
#include <math.h>

// Oscillator: XLA ReduceWindowRewriter (base_length=16) cumsum association +
// XLA-GPU scale chain:  d1 = fl(cs - cs0); d2 = fl(d1 * fl32(2pi));
//                       d3 = div.full.f32(d2, 16000);  x = fl(d3 + pm)
// div.full.f32 replicates XLA GPU's non-IEEE f32 divide bit-exactly.

#define B_DIM 64
#define F_DIM 4096
#define HOP 64
#define NHOPS (B_DIM * F_DIM)          // 262144
#define NOUT (NHOPS * HOP)             // 16777216
#define NQ 16384                       // strips of 16 per row

__device__ float g_R1[B_DIM * NQ];     // 4 MB: inclusive scan of strip sums (rw16)

// ---------------- Kernel A: per-row strip-mined scan tables (rw16) ----------------
__global__ void __launch_bounds__(512) prep_k(const float* __restrict__ freq) {
    __shared__ float sm16[4096];   // sequential 16-fold of f_j per hop
    __shared__ float S1[1024];
    __shared__ float R2s[1024];
    __shared__ float S2[64];
    __shared__ float I3s[64];
    __shared__ float R3s[64];
    __shared__ float R4s[4];

    const int row = blockIdx.x;
    const int tid = threadIdx.x;   // 512
    const float* fr = freq + row * F_DIM;

    for (int j = tid; j < 4096; j += 512) {
        float f = fr[j];
        float s = 0.0f;
        #pragma unroll
        for (int i = 0; i < 16; i++) s = __fadd_rn(s, f);
        sm16[j] = s;
    }
    __syncthreads();

    // Level-1 strips: strip a covers V1[16a..16a+15], V1[b] = sm16[b/4]
    float I1a[2][16];
    #pragma unroll
    for (int u = 0; u < 2; u++) {
        int a = tid + u * 512;
        float acc = 0.0f;
        #pragma unroll
        for (int i = 0; i < 16; i++) {
            acc = __fadd_rn(acc, sm16[4 * a + (i >> 2)]);
            I1a[u][i] = acc;
        }
        S1[a] = acc;
    }
    __syncthreads();

    if (tid < 64) {
        float acc = 0.0f;
        #pragma unroll
        for (int i = 0; i < 16; i++) acc = __fadd_rn(acc, S1[16 * tid + i]);
        S2[tid] = acc;
    }
    __syncthreads();

    if (tid < 4) {
        float acc = 0.0f;
        #pragma unroll
        for (int i = 0; i < 16; i++) {
            acc = __fadd_rn(acc, S2[16 * tid + i]);
            I3s[16 * tid + i] = acc;
        }
    }
    __syncthreads();
    if (tid == 0) {
        float acc = 0.0f;
        #pragma unroll
        for (int d = 0; d < 4; d++) {
            acc = __fadd_rn(acc, I3s[16 * d + 15]);
            R4s[d] = acc;
        }
    }
    __syncthreads();
    if (tid < 64) {
        int r = tid;
        R3s[r] = (r >= 16) ? __fadd_rn(I3s[r], R4s[(r >> 4) - 1]) : I3s[r];
    }
    __syncthreads();
    if (tid < 64) {
        int c = tid;
        float acc = 0.0f;
        #pragma unroll
        for (int i = 0; i < 16; i++) {
            acc = __fadd_rn(acc, S1[16 * c + i]);
            R2s[16 * c + i] = (c > 0) ? __fadd_rn(acc, R3s[c - 1]) : acc;
        }
    }
    __syncthreads();
    #pragma unroll
    for (int u = 0; u < 2; u++) {
        int a = tid + u * 512;
        float off = (a > 0) ? R2s[a - 1] : 0.0f;
        #pragma unroll
        for (int i = 0; i < 16; i++) {
            float v = (a > 0) ? __fadd_rn(I1a[u][i], off) : I1a[u][i];
            g_R1[row * NQ + 16 * a + i] = v;
        }
    }
}

// ---------------- accurate float sin (abs err ~1e-7 for |x| <= ~2e5) ----------------
__device__ __forceinline__ float fast_sin(float x) {
    float n = rintf(x * 0.63661977236758134308f);
    int   q = (int)n;
    const float P1 = 1.57079637050628662109375f;   // fl32(pi/2)
    const float P2 = -4.37113900018624283e-08f;    // pi/2 - P1
    float r = fmaf(-n, P1, x);
    r = fmaf(-n, P2, r);
    float r2 = r * r;
    float sp = fmaf(-1.9515295891e-4f, r2, 8.3321608736e-3f);
    sp = fmaf(sp, r2, -1.6666654611e-1f);
    float sinr = fmaf(r * r2, sp, r);
    float cp = fmaf(2.443315711809948e-5f, r2, -1.388731625493765e-3f);
    cp = fmaf(cp, r2, 4.166664568298827e-2f);
    float cosr = fmaf(r2 * r2, cp, fmaf(-0.5f, r2, 1.0f));
    float res = (q & 1) ? cosr : sinr;
    if (q & 2) res = -res;
    return res;
}

__device__ __forceinline__ float div_full(float a, float b) {
    float r;
    asm("div.full.f32 %0, %1, %2;" : "=f"(r) : "f"(a), "f"(b));
    return r;
}

// ---------------- Kernel B: 16 threads/hop, 1 float4 each ----------------
__global__ void __launch_bounds__(256) osc_k(const float* __restrict__ freq,
                                             const float* __restrict__ pmod,
                                             float* __restrict__ out) {
    const int gq  = blockIdx.x * 256 + threadIdx.x;   // float4 index
    const int hop = gq >> 4;
    const int s   = gq & 15;
    const int row = hop >> 12;
    const int j   = hop & 4095;

    const float f   = __ldg(freq + hop);
    const float f0  = __ldg(freq + (row << 12));      // cs[0] = fl(0+f_0) = f_0
    const int   q0  = j * 4 + (s >> 2);               // per-row strip index
    const float R1v = (q0 > 0) ? __ldg(g_R1 + row * NQ + q0 - 1) : 0.0f;
    const float4 p4 = __ldg((const float4*)pmod + gq);

    // I0: sequential prefix within the strip of 16 (positions (s&3)*4 + 1..4)
    const int p0 = (s & 3) * 4;
    float sm = 0.0f;
    #pragma unroll
    for (int i = 0; i < 12; i++) if (i < p0) sm = __fadd_rn(sm, f);

    const float TWO_PI_F = 6.2831853071795864769f;    // 0x40C90FDB

    float pm[4] = {p4.x, p4.y, p4.z, p4.w};
    float ov[4];
#pragma unroll
    for (int l = 0; l < 4; l++) {
        sm = __fadd_rn(sm, f);                        // I0[t]
        float cs = (q0 > 0) ? __fadd_rn(sm, R1v) : sm;
        float d1 = __fadd_rn(cs, -f0);
        float d2 = __fmul_rn(d1, TWO_PI_F);
        float d3 = div_full(d2, 16000.0f);            // XLA GPU non-IEEE divide
        float x  = __fadd_rn(d3, pm[l]);
        ov[l] = fast_sin(x);
    }
    ((float4*)out)[gq] = make_float4(ov[0], ov[1], ov[2], ov[3]);
}

extern "C" void kernel_launch(void* const* d_in, const int* in_sizes, int n_in,
                              void* d_out, int out_size) {
    const float* freq = (const float*)d_in[0];   // [64, 4096]
    const float* pmod = (const float*)d_in[1];   // [64, 262144]
    float* out = (float*)d_out;                  // [64, 262144]

    prep_k<<<B_DIM, 512>>>(freq);
    osc_k<<<(NOUT / 4) / 256, 256>>>(freq, pmod, out);
}

// round 10
// speedup vs baseline: 1.7583x; 1.7583x over previous
#include <cuda_runtime.h>
#include <cuda_bf16.h>
#include <math.h>

// Oscillator: XLA rw16 cumsum association + div.full.f32 scale chain (bit-exact
// vs reference through x); sin via MUFU approx (margin: threshold 1e-3, err ~1e-6).

#define B_DIM 64
#define F_DIM 4096
#define HOP 64
#define NHOPS (B_DIM * F_DIM)          // 262144
#define NOUT (NHOPS * HOP)             // 16777216
#define NQ 16384                       // strips of 16 per row

__device__ float  g_R1z[B_DIM * NQ];   // zero-shifted: [0]=0, [q]=R1[q-1]
__device__ float4 g_b4[NHOPS];         // per hop: (f, fold4, fold8, fold12)

// ---------------- Kernel A: rw16 scan tables + per-hop fold bases ----------------
__global__ void __launch_bounds__(512) prep_k(const float* __restrict__ freq) {
    __shared__ float sm16[4096];
    __shared__ float S1[1024];
    __shared__ float R2s[1024];
    __shared__ float S2[64];
    __shared__ float I3s[64];
    __shared__ float R3s[64];
    __shared__ float R4s[4];

    const int row = blockIdx.x;
    const int tid = threadIdx.x;   // 512
    const float* fr = freq + row * F_DIM;

    for (int j = tid; j < 4096; j += 512) {
        float f = fr[j];
        float s = 0.0f, c4 = 0.0f, c8 = 0.0f, c12 = 0.0f;
        #pragma unroll
        for (int i = 0; i < 16; i++) {
            s = __fadd_rn(s, f);
            if (i == 3)  c4  = s;
            if (i == 7)  c8  = s;
            if (i == 11) c12 = s;
        }
        sm16[j] = s;
        g_b4[row * F_DIM + j] = make_float4(f, c4, c8, c12);
    }
    __syncthreads();

    // Level-1 strips: strip a covers V1[16a..16a+15], V1[b] = sm16[b/4]
    float I1a[2][16];
    #pragma unroll
    for (int u = 0; u < 2; u++) {
        int a = tid + u * 512;
        float acc = 0.0f;
        #pragma unroll
        for (int i = 0; i < 16; i++) {
            acc = __fadd_rn(acc, sm16[4 * a + (i >> 2)]);
            I1a[u][i] = acc;
        }
        S1[a] = acc;
    }
    __syncthreads();

    if (tid < 64) {
        float acc = 0.0f;
        #pragma unroll
        for (int i = 0; i < 16; i++) acc = __fadd_rn(acc, S1[16 * tid + i]);
        S2[tid] = acc;
    }
    __syncthreads();

    if (tid < 4) {
        float acc = 0.0f;
        #pragma unroll
        for (int i = 0; i < 16; i++) {
            acc = __fadd_rn(acc, S2[16 * tid + i]);
            I3s[16 * tid + i] = acc;
        }
    }
    __syncthreads();
    if (tid == 0) {
        float acc = 0.0f;
        #pragma unroll
        for (int d = 0; d < 4; d++) {
            acc = __fadd_rn(acc, I3s[16 * d + 15]);
            R4s[d] = acc;
        }
        g_R1z[row * NQ] = 0.0f;      // zero-shift entry
    }
    __syncthreads();
    if (tid < 64) {
        int r = tid;
        R3s[r] = (r >= 16) ? __fadd_rn(I3s[r], R4s[(r >> 4) - 1]) : I3s[r];
    }
    __syncthreads();
    if (tid < 64) {
        int c = tid;
        float acc = 0.0f;
        #pragma unroll
        for (int i = 0; i < 16; i++) {
            acc = __fadd_rn(acc, S1[16 * c + i]);
            R2s[16 * c + i] = (c > 0) ? __fadd_rn(acc, R3s[c - 1]) : acc;
        }
    }
    __syncthreads();
    // R1[q] = fl(I1[q] + R2[q/16-1])  -> zero-shifted global at q+1
    #pragma unroll
    for (int u = 0; u < 2; u++) {
        int a = tid + u * 512;
        float off = (a > 0) ? R2s[a - 1] : 0.0f;
        #pragma unroll
        for (int i = 0; i < 16; i++) {
            int idx = 16 * a + i;
            float v = (a > 0) ? __fadd_rn(I1a[u][i], off) : I1a[u][i];
            if (idx < NQ - 1) g_R1z[row * NQ + idx + 1] = v;
        }
    }
}

__device__ __forceinline__ float div_full(float a, float b) {
    float r;
    asm("div.full.f32 %0, %1, %2;" : "=f"(r) : "f"(a), "f"(b));
    return r;
}

// ---------------- Kernel B: 16 threads/hop, 1 float4 each ----------------
__global__ void __launch_bounds__(256) osc_k(const float* __restrict__ freq,
                                             const float* __restrict__ pmod,
                                             float* __restrict__ out) {
    const int gq  = blockIdx.x * 256 + threadIdx.x;   // float4 index
    const int hop = gq >> 4;
    const int s   = gq & 15;
    const int row = gq >> 16;                          // 65536 float4 per row

    const float4 b4 = __ldg(&g_b4[hop]);               // (f, c4, c8, c12)
    const float  f  = b4.x;
    const float  f0 = __ldg(freq + (row << 12));       // cs[0] = f_0
    const float  R1v = __ldg(&g_R1z[row * NQ + ((gq >> 2) & (NQ - 1))]);
    const float4 p4 = __ldg((const float4*)pmod + gq);

    // quarter base: sequential fold of (s&3)*4 copies of f (precomputed, bit-equal)
    const int s3 = s & 3;
    float a  = (s3 & 1) ? b4.y : 0.0f;                 // c4 or 0
    float b  = (s3 & 1) ? b4.w : b4.z;                 // c12 or c8
    float sm = (s3 & 2) ? b : a;

    const float TWO_PI_F  = 6.2831853071795864769f;    // 0x40C90FDB
    const float TWO_O_PI  = 0.63661977236758134308f;
    const float MAGIC     = 12582912.0f;               // 1.5 * 2^23
    const float P1 = 1.57079637050628662109375f;       // fl32(pi/2)
    const float P2 = -4.37113900018624283e-08f;        // pi/2 - P1

    float pm[4] = {p4.x, p4.y, p4.z, p4.w};
    float ov[4];
#pragma unroll
    for (int l = 0; l < 4; l++) {
        sm = __fadd_rn(sm, f);                         // I0[t] (bit-exact chain)
        float cs = __fadd_rn(sm, R1v);                 // +0 exact for strip 0
        float d1 = __fadd_rn(cs, -f0);
        float d2 = __fmul_rn(d1, TWO_PI_F);
        float d3 = div_full(d2, 16000.0f);             // XLA GPU divide
        float x  = __fadd_rn(d3, pm[l]);
        // sin: magic-round quadrant + 2-word FMA reduction + MUFU approx
        float v  = __fmul_rn(x, TWO_O_PI);
        float t  = __fadd_rn(v, MAGIC);
        float n  = __fadd_rn(t, -MAGIC);
        int   q  = __float_as_int(t);
        float r  = fmaf(-n, P1, x);
        r        = fmaf(-n, P2, r);
        float sr, cr;
        asm("sin.approx.f32 %0, %1;" : "=f"(sr) : "f"(r));
        asm("cos.approx.f32 %0, %1;" : "=f"(cr) : "f"(r));
        float res = (q & 1) ? cr : sr;
        ov[l] = __int_as_float(__float_as_int(res) ^ ((q & 2) << 30));
    }
    ((float4*)out)[gq] = make_float4(ov[0], ov[1], ov[2], ov[3]);
}

extern "C" void kernel_launch(void* const* d_in, const int* in_sizes, int n_in,
                              void* d_out, int out_size) {
    const float* freq = (const float*)d_in[0];   // [64, 4096]
    const float* pmod = (const float*)d_in[1];   // [64, 262144]
    float* out = (float*)d_out;                  // [64, 262144]

    prep_k<<<B_DIM, 512>>>(freq);
    osc_k<<<(NOUT / 4) / 256, 256>>>(freq, pmod, out);
}